// round 12
// baseline (speedup 1.0000x reference)
#include <cuda_runtime.h>
#include <cuda_bf16.h>

// Calc_Xi_And_LogLikelihood — FINAL converged kernel (R11 artifact, verbatim)
//   mu, sigma, eps : float32 [64, 16, 200, 64]
//   xi  = mu + (sigma + 1e-5) * eps                 -> first 13,107,200 floats of d_out
//   LL[bs,nc] = -0.5*sum eps^2 - sum log s - TS*(D/2)*log(2*pi)  -> next 1024 floats
//   (z = (xi-mu)/s == eps analytically; fp32 delta ~1e-4 abs on |LL|~5e3, far under tol)
//
// Convergence evidence (R2-R11):
//  * Kernel window 30.75us @ 76.0% DRAM (6.0 TB/s) — the HBM mixed-stream
//    (3:1 read:write turnaround) ceiling for the compulsory 209 MB/replay.
//  * Bench = kernel + ~4.6us fixed graph-replay gap +/- 1.5us harness noise
//    (established by the R10 byte-identical revert experiment).
//  * Measured WORSE/NEUTRAL: 2048-CTA split, L2 evict_last pinning, 256-bit
//    loads, 160-thread single-wave, dual accumulators, alternate schedules.
//  * Measured WINS (all kept): __stcs streaming stores (+9% DRAM util),
//    __ldg read-only path, 320thr/occ4/unroll-5 schedule, exponent-stripped
//    4:1-batched FMA-only poly-log (no MUFU, no division, no divergence).

#define BS_ 64
#define NC_ 16
#define TS_ 200
#define D_  64

constexpr int ROW_ELEMS  = TS_ * D_;        // 12800 contiguous floats per (bs,nc)
constexpr int ROWS       = BS_ * NC_;       // 1024
constexpr int VEC        = ROW_ELEMS / 4;   // 3200 float4 per row
constexpr int THREADS    = 320;
constexpr int PER_THREAD = VEC / THREADS;   // 10, exact
constexpr int NWARPS     = THREADS / 32;    // 10

constexpr float LL_CONST = 11762.413225019809f;   // TS*(D/2)*log(2*pi)
constexpr float LN2      = 0.69314718055994531f;

__global__ __launch_bounds__(THREADS, 4)
void calc_xi_ll_kernel(const float* __restrict__ mu,
                       const float* __restrict__ sigma,
                       const float* __restrict__ eps,
                       float* __restrict__ xi,
                       float* __restrict__ ll) {
    const int row = blockIdx.x;                       // (bs*NC + nc)
    const size_t base = (size_t)row * VEC;            // float4 index

    const float4* __restrict__ mu4 = (const float4*)mu  + base;
    const float4* __restrict__ sg4 = (const float4*)sigma + base;
    const float4* __restrict__ ep4 = (const float4*)eps + base;
    float4* __restrict__ xi4       = (float4*)xi + base;

    float ss   = 0.0f;   // sum eps^2
    float ls   = 0.0f;   // sum ln(mantissa products)
    int   ksum = 0;      // sum of exponents

    #pragma unroll 5
    for (int j = 0; j < PER_THREAD; j++) {
        const int i = threadIdx.x + j * THREADS;
        float4 m = __ldg(&mu4[i]);
        float4 g = __ldg(&sg4[i]);
        float4 e = __ldg(&ep4[i]);

        float sx = g.x + 1e-5f;
        float sy = g.y + 1e-5f;
        float sz = g.z + 1e-5f;
        float sw = g.w + 1e-5f;

        float4 o;
        o.x = fmaf(sx, e.x, m.x);
        o.y = fmaf(sy, e.y, m.y);
        o.z = fmaf(sz, e.z, m.z);
        o.w = fmaf(sw, e.w, m.w);
        __stcs(&xi4[i], o);                           // streaming store: keep L2 for inputs

        ss = fmaf(e.x, e.x, ss);
        ss = fmaf(e.y, e.y, ss);
        ss = fmaf(e.z, e.z, ss);
        ss = fmaf(e.w, e.w, ss);

        // Strip exponents (ALU pipe), keep mantissas in [2/3, 4/3)
        int bx = __float_as_int(sx); int ex = (bx - 0x3f2aaaab) & 0xff800000;
        int by = __float_as_int(sy); int ey = (by - 0x3f2aaaab) & 0xff800000;
        int bz = __float_as_int(sz); int ez = (bz - 0x3f2aaaab) & 0xff800000;
        int bw = __float_as_int(sw); int ew = (bw - 0x3f2aaaab) & 0xff800000;
        ksum += (ex >> 23) + (ey >> 23) + (ez >> 23) + (ew >> 23);

        float p = (__int_as_float(bx - ex) * __int_as_float(by - ey)) *
                  (__int_as_float(bz - ez) * __int_as_float(bw - ew));
        // p in [0.198, 3.16]; one more exponent strip, then one poly-log
        int bp = __float_as_int(p); int ep = (bp - 0x3f2aaaab) & 0xff800000;
        ksum += (ep >> 23);
        float t = __int_as_float(bp - ep) - 1.0f;     // t in [-1/3, 1/3)
        // ln(1+t) = t + t^2 * q(t),  q = -1/2 + t/3 - t^2/4 + t^3/5 - t^4/6
        float q = -0.16666667f;
        q = fmaf(q, t,  0.20000000f);
        q = fmaf(q, t, -0.25000000f);
        q = fmaf(q, t,  0.33333333f);
        q = fmaf(q, t, -0.50000000f);
        ls += t;
        ls = fmaf(q, t * t, ls);
    }

    float lsum = fmaf((float)ksum, LN2, ls);

    // Intra-warp tree reduce (two scalars)
    #pragma unroll
    for (int off = 16; off > 0; off >>= 1) {
        ss   += __shfl_down_sync(0xffffffffu, ss, off);
        lsum += __shfl_down_sync(0xffffffffu, lsum, off);
    }

    __shared__ float s_ss[NWARPS];
    __shared__ float s_ls[NWARPS];
    const int wid = threadIdx.x >> 5;
    const int lid = threadIdx.x & 31;
    if (lid == 0) { s_ss[wid] = ss; s_ls[wid] = lsum; }
    __syncthreads();

    if (wid == 0) {
        ss   = (lid < NWARPS) ? s_ss[lid] : 0.0f;
        lsum = (lid < NWARPS) ? s_ls[lid] : 0.0f;
        #pragma unroll
        for (int off = 8; off > 0; off >>= 1) {
            ss   += __shfl_down_sync(0xffffffffu, ss, off);
            lsum += __shfl_down_sync(0xffffffffu, lsum, off);
        }
        if (lid == 0) {
            ll[row] = fmaf(-0.5f, ss, -lsum) - LL_CONST;
        }
    }
}

extern "C" void kernel_launch(void* const* d_in, const int* in_sizes, int n_in,
                              void* d_out, int out_size) {
    const float* mu    = (const float*)d_in[0];
    const float* sigma = (const float*)d_in[1];
    const float* eps   = (const float*)d_in[2];
    float* xi = (float*)d_out;
    float* ll = xi + (size_t)ROWS * ROW_ELEMS;   // LL follows xi in the output buffer

    calc_xi_ll_kernel<<<ROWS, THREADS>>>(mu, sigma, eps, xi, ll);
}

// round 13
// speedup vs baseline: 1.0362x; 1.0362x over previous
#include <cuda_runtime.h>
#include <cuda_bf16.h>

// Calc_Xi_And_LogLikelihood — FINAL converged kernel (R11 artifact, verbatim)
//   mu, sigma, eps : float32 [64, 16, 200, 64]
//   xi  = mu + (sigma + 1e-5) * eps                 -> first 13,107,200 floats of d_out
//   LL[bs,nc] = -0.5*sum eps^2 - sum log s - TS*(D/2)*log(2*pi)  -> next 1024 floats
//   (z = (xi-mu)/s == eps analytically; fp32 delta ~1e-4 abs on |LL|~5e3, far under tol)
//
// Convergence evidence (R2-R12):
//  * Kernel window reproducible at 30.75-30.85us @ 75.5-76.0% DRAM (6.0 TB/s)
//    across three runs of this binary — the HBM mixed-stream (3:1 read:write
//    turnaround) ceiling for the compulsory 209 MB/replay traffic.
//  * Bench = kernel + ~4.6us fixed graph-replay gap +/- 1.5us harness noise
//    (established by byte-identical resubmissions R10/R11/R12: 36.8/35.3/36.6).
//  * Measured WORSE/NEUTRAL: 2048-CTA split, L2 evict_last pinning, 256-bit
//    loads, 160-thread single-wave, dual accumulators, alternate schedules.
//  * Measured WINS (all kept): __stcs streaming stores (+9% DRAM util),
//    __ldg read-only path, 320thr/occ4/unroll-5 schedule, exponent-stripped
//    4:1-batched FMA-only poly-log (no MUFU, no division, no divergence).

#define BS_ 64
#define NC_ 16
#define TS_ 200
#define D_  64

constexpr int ROW_ELEMS  = TS_ * D_;        // 12800 contiguous floats per (bs,nc)
constexpr int ROWS       = BS_ * NC_;       // 1024
constexpr int VEC        = ROW_ELEMS / 4;   // 3200 float4 per row
constexpr int THREADS    = 320;
constexpr int PER_THREAD = VEC / THREADS;   // 10, exact
constexpr int NWARPS     = THREADS / 32;    // 10

constexpr float LL_CONST = 11762.413225019809f;   // TS*(D/2)*log(2*pi)
constexpr float LN2      = 0.69314718055994531f;

__global__ __launch_bounds__(THREADS, 4)
void calc_xi_ll_kernel(const float* __restrict__ mu,
                       const float* __restrict__ sigma,
                       const float* __restrict__ eps,
                       float* __restrict__ xi,
                       float* __restrict__ ll) {
    const int row = blockIdx.x;                       // (bs*NC + nc)
    const size_t base = (size_t)row * VEC;            // float4 index

    const float4* __restrict__ mu4 = (const float4*)mu  + base;
    const float4* __restrict__ sg4 = (const float4*)sigma + base;
    const float4* __restrict__ ep4 = (const float4*)eps + base;
    float4* __restrict__ xi4       = (float4*)xi + base;

    float ss   = 0.0f;   // sum eps^2
    float ls   = 0.0f;   // sum ln(mantissa products)
    int   ksum = 0;      // sum of exponents

    #pragma unroll 5
    for (int j = 0; j < PER_THREAD; j++) {
        const int i = threadIdx.x + j * THREADS;
        float4 m = __ldg(&mu4[i]);
        float4 g = __ldg(&sg4[i]);
        float4 e = __ldg(&ep4[i]);

        float sx = g.x + 1e-5f;
        float sy = g.y + 1e-5f;
        float sz = g.z + 1e-5f;
        float sw = g.w + 1e-5f;

        float4 o;
        o.x = fmaf(sx, e.x, m.x);
        o.y = fmaf(sy, e.y, m.y);
        o.z = fmaf(sz, e.z, m.z);
        o.w = fmaf(sw, e.w, m.w);
        __stcs(&xi4[i], o);                           // streaming store: keep L2 for inputs

        ss = fmaf(e.x, e.x, ss);
        ss = fmaf(e.y, e.y, ss);
        ss = fmaf(e.z, e.z, ss);
        ss = fmaf(e.w, e.w, ss);

        // Strip exponents (ALU pipe), keep mantissas in [2/3, 4/3)
        int bx = __float_as_int(sx); int ex = (bx - 0x3f2aaaab) & 0xff800000;
        int by = __float_as_int(sy); int ey = (by - 0x3f2aaaab) & 0xff800000;
        int bz = __float_as_int(sz); int ez = (bz - 0x3f2aaaab) & 0xff800000;
        int bw = __float_as_int(sw); int ew = (bw - 0x3f2aaaab) & 0xff800000;
        ksum += (ex >> 23) + (ey >> 23) + (ez >> 23) + (ew >> 23);

        float p = (__int_as_float(bx - ex) * __int_as_float(by - ey)) *
                  (__int_as_float(bz - ez) * __int_as_float(bw - ew));
        // p in [0.198, 3.16]; one more exponent strip, then one poly-log
        int bp = __float_as_int(p); int ep = (bp - 0x3f2aaaab) & 0xff800000;
        ksum += (ep >> 23);
        float t = __int_as_float(bp - ep) - 1.0f;     // t in [-1/3, 1/3)
        // ln(1+t) = t + t^2 * q(t),  q = -1/2 + t/3 - t^2/4 + t^3/5 - t^4/6
        float q = -0.16666667f;
        q = fmaf(q, t,  0.20000000f);
        q = fmaf(q, t, -0.25000000f);
        q = fmaf(q, t,  0.33333333f);
        q = fmaf(q, t, -0.50000000f);
        ls += t;
        ls = fmaf(q, t * t, ls);
    }

    float lsum = fmaf((float)ksum, LN2, ls);

    // Intra-warp tree reduce (two scalars)
    #pragma unroll
    for (int off = 16; off > 0; off >>= 1) {
        ss   += __shfl_down_sync(0xffffffffu, ss, off);
        lsum += __shfl_down_sync(0xffffffffu, lsum, off);
    }

    __shared__ float s_ss[NWARPS];
    __shared__ float s_ls[NWARPS];
    const int wid = threadIdx.x >> 5;
    const int lid = threadIdx.x & 31;
    if (lid == 0) { s_ss[wid] = ss; s_ls[wid] = lsum; }
    __syncthreads();

    if (wid == 0) {
        ss   = (lid < NWARPS) ? s_ss[lid] : 0.0f;
        lsum = (lid < NWARPS) ? s_ls[lid] : 0.0f;
        #pragma unroll
        for (int off = 8; off > 0; off >>= 1) {
            ss   += __shfl_down_sync(0xffffffffu, ss, off);
            lsum += __shfl_down_sync(0xffffffffu, lsum, off);
        }
        if (lid == 0) {
            ll[row] = fmaf(-0.5f, ss, -lsum) - LL_CONST;
        }
    }
}

extern "C" void kernel_launch(void* const* d_in, const int* in_sizes, int n_in,
                              void* d_out, int out_size) {
    const float* mu    = (const float*)d_in[0];
    const float* sigma = (const float*)d_in[1];
    const float* eps   = (const float*)d_in[2];
    float* xi = (float*)d_out;
    float* ll = xi + (size_t)ROWS * ROW_ELEMS;   // LL follows xi in the output buffer

    calc_xi_ll_kernel<<<ROWS, THREADS>>>(mu, sigma, eps, xi, ll);
}